// round 1
// baseline (speedup 1.0000x reference)
#include <cuda_runtime.h>
#include <cuda_bf16.h>
#include <cstdint>

// Problem constants
#define BW_   2048          // batch * windows
#define NTOK  49            // tokens per window
#define NH_   12            // heads
#define HD_   32            // head dim
#define DIM_  384
#define M_    (BW_ * NTOK)  // 100352
#define K_    DIM_          // 384

// Scratch (device globals; allocation inside kernel_launch is forbidden)
__device__ float g_Q[BW_ * NH_ * NTOK * HD_];   // [B,H,49,32], pre-scaled
__device__ float g_K[BW_ * NH_ * NTOK * HD_];
__device__ float g_V[BW_ * NH_ * NTOK * HD_];
__device__ float g_AO[BW_ * NTOK * DIM_];       // attention output [B,49,384]

// ---------------------------------------------------------------------------
// tf32 helpers
// ---------------------------------------------------------------------------
__device__ __forceinline__ uint32_t f2tf(float f) {
    uint32_t u;
    asm("cvt.rna.tf32.f32 %0, %1;" : "=r"(u) : "f"(f));
    return u;
}

__device__ __forceinline__ void mma_tf32(float* c, const uint32_t* a, const uint32_t* b) {
    asm volatile(
        "mma.sync.aligned.m16n8k8.row.col.f32.tf32.tf32.f32 "
        "{%0,%1,%2,%3}, {%4,%5,%6,%7}, {%8,%9}, {%0,%1,%2,%3};\n"
        : "+f"(c[0]), "+f"(c[1]), "+f"(c[2]), "+f"(c[3])
        : "r"(a[0]), "r"(a[1]), "r"(a[2]), "r"(a[3]), "r"(b[0]), "r"(b[1]));
}

// ---------------------------------------------------------------------------
// tf32 GEMM:  C[M,N] = A[M,K] * B[N,K]^T (+ bias)
// MODE 0: A = x, writes scattered Q/K/V (N = 1152)
// MODE 1: A = g_AO, writes out[m*384+n] (N = 384)
// BM=128, BN=64, BK=16, 256 threads, 8 warps as 4(m) x 2(n), warp tile 32x32
// ---------------------------------------------------------------------------
#define BM 128
#define BN 64
#define BK 16
#define ASTR 136   // BM + 8  -> conflict-free fragment loads (stride mod 32 == 8)
#define BSTR 72    // BN + 8

template <int MODE>
__global__ __launch_bounds__(256, 2)
void gemm_kernel(const float* __restrict__ A,
                 const float* __restrict__ B,
                 const float* __restrict__ bias,
                 float* __restrict__ out) {
    __shared__ uint32_t As[2][BK][ASTR];
    __shared__ uint32_t Bs[2][BK][BSTR];

    const float* Abase = (MODE == 0) ? A : (const float*)g_AO;

    const int tid  = threadIdx.x;
    const int bm   = blockIdx.x * BM;
    const int bn   = blockIdx.y * BN;
    const int warp = tid >> 5;
    const int lane = tid & 31;
    const int wm   = warp & 3;        // 0..3 along m
    const int wn   = warp >> 2;       // 0..1 along n
    const int lm   = lane >> 2;       // groupID
    const int lk   = lane & 3;        // threadID_in_group

    // loader mapping (coalesced LDG.128 along K)
    const int a_m  = tid >> 2;                 // 0..63
    const int a_k0 = (tid & 3) * 4;            // 0,4,8,12
    const int b_n  = tid >> 2;                 // 0..63
    const int b_k0 = (tid & 3) * 4;

    const float* Aptr = Abase + (size_t)(bm + a_m) * K_ + a_k0;
    const float* Bptr = B + (size_t)(bn + b_n) * K_ + b_k0;

    float acc[2][4][4];
#pragma unroll
    for (int mi = 0; mi < 2; ++mi)
#pragma unroll
        for (int ni = 0; ni < 4; ++ni)
#pragma unroll
            for (int e = 0; e < 4; ++e) acc[mi][ni][e] = 0.f;

    const int KT = K_ / BK;   // 24

    // prologue: load tile 0 and commit to buffer 0
    float4 ra0 = *(const float4*)(Aptr);
    float4 ra1 = *(const float4*)(Aptr + 64 * K_);
    float4 rb  = *(const float4*)(Bptr);
    {
        float va[4] = {ra0.x, ra0.y, ra0.z, ra0.w};
        float vb[4] = {ra1.x, ra1.y, ra1.z, ra1.w};
        float vc[4] = {rb.x, rb.y, rb.z, rb.w};
#pragma unroll
        for (int j = 0; j < 4; ++j) {
            int jj = (j + tid) & 3;    // stagger to dodge STS bank conflicts
            As[0][a_k0 + jj][a_m]      = f2tf(va[jj]);
            As[0][a_k0 + jj][a_m + 64] = f2tf(vb[jj]);
            Bs[0][b_k0 + jj][b_n]      = f2tf(vc[jj]);
        }
    }
    __syncthreads();

    int buf = 0;
    for (int kt = 0; kt < KT; ++kt) {
        const bool more = (kt + 1 < KT);
        float4 na0, na1, nb;
        if (more) {
            na0 = *(const float4*)(Aptr + (kt + 1) * BK);
            na1 = *(const float4*)(Aptr + 64 * K_ + (kt + 1) * BK);
            nb  = *(const float4*)(Bptr + (kt + 1) * BK);
        }

#pragma unroll
        for (int kk = 0; kk < BK; kk += 8) {
            uint32_t af[2][4];
            uint32_t bf[4][2];
#pragma unroll
            for (int mi = 0; mi < 2; ++mi) {
                int r = wm * 32 + mi * 16 + lm;
                af[mi][0] = As[buf][kk + lk][r];
                af[mi][1] = As[buf][kk + lk][r + 8];
                af[mi][2] = As[buf][kk + 4 + lk][r];
                af[mi][3] = As[buf][kk + 4 + lk][r + 8];
            }
#pragma unroll
            for (int ni = 0; ni < 4; ++ni) {
                int c = wn * 32 + ni * 8 + lm;
                bf[ni][0] = Bs[buf][kk + lk][c];
                bf[ni][1] = Bs[buf][kk + 4 + lk][c];
            }
#pragma unroll
            for (int mi = 0; mi < 2; ++mi)
#pragma unroll
                for (int ni = 0; ni < 4; ++ni)
                    mma_tf32(acc[mi][ni], af[mi], bf[ni]);
        }

        if (more) {
            int nbuf = buf ^ 1;
            float va[4] = {na0.x, na0.y, na0.z, na0.w};
            float vb[4] = {na1.x, na1.y, na1.z, na1.w};
            float vc[4] = {nb.x, nb.y, nb.z, nb.w};
#pragma unroll
            for (int j = 0; j < 4; ++j) {
                int jj = (j + tid) & 3;
                As[nbuf][a_k0 + jj][a_m]      = f2tf(va[jj]);
                As[nbuf][a_k0 + jj][a_m + 64] = f2tf(vb[jj]);
                Bs[nbuf][b_k0 + jj][b_n]      = f2tf(vc[jj]);
            }
            __syncthreads();
            buf = nbuf;
        }
    }

    // ---------------- epilogue ----------------
    const int n0 = bn + wn * 32;     // warp's 32 output cols, 32-aligned

    if (MODE == 0) {
        const int which = n0 / DIM_;             // 0=q 1=k 2=v
        const int h     = (n0 % DIM_) / HD_;
        const float scl = (which == 0) ? 0.17677669529663687f : 1.0f;  // 1/sqrt(32)
        float* dst = (which == 0) ? g_Q : ((which == 1) ? g_K : g_V);
#pragma unroll
        for (int mi = 0; mi < 2; ++mi) {
#pragma unroll
            for (int e = 0; e < 2; ++e) {
                int row  = bm + wm * 32 + mi * 16 + lm + e * 8;
                int bwin = row / NTOK;
                int t    = row - bwin * NTOK;
                size_t obase = ((size_t)(bwin * NH_ + h) * NTOK + t) * HD_;
#pragma unroll
                for (int ni = 0; ni < 4; ++ni) {
                    int d = ni * 8 + lk * 2;
                    float v0 = (acc[mi][ni][e * 2 + 0] + bias[n0 + d])     * scl;
                    float v1 = (acc[mi][ni][e * 2 + 1] + bias[n0 + d + 1]) * scl;
                    float2 w = make_float2(v0, v1);
                    *(float2*)(dst + obase + d) = w;
                }
            }
        }
    } else {
#pragma unroll
        for (int mi = 0; mi < 2; ++mi) {
#pragma unroll
            for (int e = 0; e < 2; ++e) {
                int row = bm + wm * 32 + mi * 16 + lm + e * 8;
#pragma unroll
                for (int ni = 0; ni < 4; ++ni) {
                    int n = n0 + ni * 8 + lk * 2;
                    float v0 = acc[mi][ni][e * 2 + 0] + bias[n];
                    float v1 = acc[mi][ni][e * 2 + 1] + bias[n + 1];
                    float2 w = make_float2(v0, v1);
                    *(float2*)(out + (size_t)row * DIM_ + n) = w;
                }
            }
        }
    }
}

// ---------------------------------------------------------------------------
// Window attention: one CTA (128 threads) per (window, head)
// ---------------------------------------------------------------------------
__global__ __launch_bounds__(128)
void attn_kernel(const float* __restrict__ table) {
    __shared__ float sq[NTOK * 33];
    __shared__ float sk[NTOK * 33];
    __shared__ float sv[NTOK * 33];
    __shared__ float sS[NTOK * NTOK];
    __shared__ float sbias[169];           // (2*7-1)^2

    const int tid = threadIdx.x;
    const int bw  = blockIdx.x / NH_;
    const int h   = blockIdx.x % NH_;
    const size_t base = ((size_t)(bw * NH_ + h) * NTOK) * HD_;

    // load q, k, v (float4 gmem, scalar STS into padded rows)
    for (int i = tid; i < (NTOK * HD_) / 4; i += 128) {   // 392 float4
        int row = i >> 3;
        int c4  = (i & 7) * 4;
        float4 fq = *(const float4*)(g_Q + base + i * 4);
        float4 fk = *(const float4*)(g_K + base + i * 4);
        float4 fv = *(const float4*)(g_V + base + i * 4);
        int o = row * 33 + c4;
        sq[o] = fq.x; sq[o + 1] = fq.y; sq[o + 2] = fq.z; sq[o + 3] = fq.w;
        sk[o] = fk.x; sk[o + 1] = fk.y; sk[o + 2] = fk.z; sk[o + 3] = fk.w;
        sv[o] = fv.x; sv[o + 1] = fv.y; sv[o + 2] = fv.z; sv[o + 3] = fv.w;
    }
    // bias column for this head
    for (int i = tid; i < 169; i += 128) sbias[i] = table[i * NH_ + h];
    __syncthreads();

    // scores S[n][m] = q[n] . k[m] + bias(n,m)
    for (int s = tid; s < NTOK * NTOK; s += 128) {
        int n = s / NTOK;
        int m = s - n * NTOK;
        const float* qr = sq + n * 33;
        const float* kr = sk + m * 33;
        float acc = 0.f;
#pragma unroll
        for (int kk = 0; kk < HD_; ++kk) acc += qr[kk] * kr[kk];
        int di = n / 7 - m / 7 + 6;
        int dj = (n % 7) - (m % 7) + 6;
        sS[s] = acc + sbias[di * 13 + dj];
    }
    __syncthreads();

    // softmax over m (warp per row)
    const int warp = tid >> 5, lane = tid & 31;
    for (int n = warp; n < NTOK; n += 4) {
        float v0 = sS[n * NTOK + lane];
        float v1 = (lane < 17) ? sS[n * NTOK + 32 + lane] : -1e30f;
        float mx = fmaxf(v0, v1);
#pragma unroll
        for (int o = 16; o > 0; o >>= 1) mx = fmaxf(mx, __shfl_xor_sync(0xffffffff, mx, o));
        float e0 = __expf(v0 - mx);
        float e1 = (lane < 17) ? __expf(v1 - mx) : 0.f;
        float sm = e0 + e1;
#pragma unroll
        for (int o = 16; o > 0; o >>= 1) sm += __shfl_xor_sync(0xffffffff, sm, o);
        float inv = __frcp_rn(sm);
        sS[n * NTOK + lane] = e0 * inv;
        if (lane < 17) sS[n * NTOK + 32 + lane] = e1 * inv;
    }
    __syncthreads();

    // O[n][d] = sum_m P[n][m] * V[m][d];  write AO[b][n][h*32+d]
    for (int o = tid; o < NTOK * HD_; o += 128) {
        int n = o >> 5;
        int d = o & 31;
        const float* pr = sS + n * NTOK;
        float acc = 0.f;
#pragma unroll 7
        for (int m = 0; m < NTOK; ++m) acc += pr[m] * sv[m * 33 + d];
        g_AO[((size_t)bw * NTOK + n) * DIM_ + h * HD_ + d] = acc;
    }
}

// ---------------------------------------------------------------------------
extern "C" void kernel_launch(void* const* d_in, const int* in_sizes, int n_in,
                              void* d_out, int out_size) {
    const float* x      = (const float*)d_in[0];
    const float* qkv_w  = (const float*)d_in[1];
    const float* qkv_b  = (const float*)d_in[2];
    const float* proj_w = (const float*)d_in[3];
    const float* proj_b = (const float*)d_in[4];
    const float* table  = (const float*)d_in[5];
    float* out = (float*)d_out;

    dim3 g1(M_ / BM, (3 * DIM_) / BN);   // 784 x 18
    gemm_kernel<0><<<g1, 256>>>(x, qkv_w, qkv_b, nullptr);

    attn_kernel<<<BW_ * NH_, 128>>>(table);

    dim3 g3(M_ / BM, DIM_ / BN);         // 784 x 6
    gemm_kernel<1><<<g3, 256>>>(nullptr, proj_w, proj_b, out);
}

// round 5
// speedup vs baseline: 2.4237x; 2.4237x over previous
#include <cuda_runtime.h>
#include <cuda_fp16.h>
#include <cstdint>

// ---------------------------------------------------------------------------
// Problem constants
// ---------------------------------------------------------------------------
#define BW_   2048          // batch * windows
#define NTOK  49            // tokens per window
#define NH_   12            // heads
#define HD_   32            // head dim
#define DIM_  384
#define M_    (BW_ * NTOK)  // 100352
#define K_    DIM_          // 384

// Scratch (device globals; allocation inside kernel_launch is forbidden)
__device__ __align__(16) float g_Q[BW_ * NH_ * NTOK * HD_];   // [B,H,49,32], pre-scaled
__device__ __align__(16) float g_K[BW_ * NH_ * NTOK * HD_];
__device__ __align__(16) float g_V[BW_ * NH_ * NTOK * HD_];
__device__ __align__(16) float g_AO[BW_ * NTOK * DIM_];       // [B,49,384]

// ---------------------------------------------------------------------------
// helpers
// ---------------------------------------------------------------------------
__device__ __forceinline__ uint32_t smem_u32(const void* p) {
    uint32_t a;
    asm("{ .reg .u64 t; cvta.to.shared.u64 t, %1; cvt.u32.u64 %0, t; }"
        : "=r"(a) : "l"(p));
    return a;
}

// SMEM layout: fp16 tile rows of 32 elements = 64 bytes/row.
// byte(row, kb) = row*64 + (kb ^ (((row>>1)&3)<<4))  -> conflict-free ldmatrix/STS
__device__ __forceinline__ uint32_t sw_off(int row, int kb) {
    return (uint32_t)(row * 64 + (kb ^ (((row >> 1) & 3) << 4)));
}

__device__ __forceinline__ void ldsm4(uint32_t* r, uint32_t a) {
    asm volatile("ldmatrix.sync.aligned.m8n8.x4.shared.b16 {%0,%1,%2,%3}, [%4];"
                 : "=r"(r[0]), "=r"(r[1]), "=r"(r[2]), "=r"(r[3]) : "r"(a));
}

__device__ __forceinline__ void mma16816(float* c, const uint32_t* a, const uint32_t* b) {
    asm volatile(
        "mma.sync.aligned.m16n8k16.row.col.f32.f16.f16.f32 "
        "{%0,%1,%2,%3}, {%4,%5,%6,%7}, {%8,%9}, {%0,%1,%2,%3};"
        : "+f"(c[0]), "+f"(c[1]), "+f"(c[2]), "+f"(c[3])
        : "r"(a[0]), "r"(a[1]), "r"(a[2]), "r"(a[3]), "r"(b[0]), "r"(b[1]));
}

__device__ __forceinline__ uint2 cvt4(float4 f) {
    __half2 h0 = __floats2half2_rn(f.x, f.y);
    __half2 h1 = __floats2half2_rn(f.z, f.w);
    uint2 u;
    u.x = *(uint32_t*)&h0;
    u.y = *(uint32_t*)&h1;
    return u;
}

// ---------------------------------------------------------------------------
// fp16 GEMM (f32 accumulate): C[M,N] = A[M,K] * B[N,K]^T (+bias)
// MODE 0: A = x, N=1152, epilogue scatters Q/K/V (q pre-scaled by 1/sqrt(32))
// MODE 1: A = g_AO, N=384, epilogue writes d_out
// BM=128, BN=64, BK=32, 256 threads (8 warps: 4m x 2n), warp tile 32x32.
// ---------------------------------------------------------------------------
#define BM 128
#define BN 64
#define BK 32
#define KT (K_ / BK)   // 12

template <int MODE>
__global__ __launch_bounds__(256, 2)
void gemm_fp16(const float* __restrict__ A, const float* __restrict__ Bw,
               const float* __restrict__ bias, float* __restrict__ out) {
    __shared__ __align__(16) uint8_t sA[2][BM * 64];
    __shared__ __align__(16) uint8_t sB[2][BN * 64];

    const float* Abase = (MODE == 0) ? A : (const float*)g_AO;

    const int tid  = threadIdx.x;
    const int lane = tid & 31;
    const int wid  = tid >> 5;
    const int wm   = wid & 3;     // 0..3 along m
    const int wn   = wid >> 2;    // 0..1 along n
    const int bm   = blockIdx.y * BM;
    const int bn   = blockIdx.x * BN;

    // ---- loader mapping: 8 threads per row, 1 float4 (16B gmem / 8B smem) each
    const int lrow = tid >> 3;         // 0..31
    const int lk4  = (tid & 7) * 4;    // k float index
    const int kb   = lk4 * 2;          // byte offset in fp16 row

    const float* Ap = Abase + (size_t)(bm + lrow) * K_ + lk4;
    const float* Bp = Bw    + (size_t)(bn + lrow) * K_ + lk4;

    uint32_t swA[4], swB[2];
#pragma unroll
    for (int j = 0; j < 4; ++j) swA[j] = sw_off(lrow + j * 32, kb);
#pragma unroll
    for (int j = 0; j < 2; ++j) swB[j] = sw_off(lrow + j * 32, kb);

    // ---- fragment ldmatrix offsets (kslice 0; kslice 1 = ^32)
    const int arow  = wm * 32 + (lane & 15);
    const int akb   = ((lane >> 4) & 1) * 16;
    const uint32_t aoff[2] = { sw_off(arow, akb), sw_off(arow + 16, akb) };

    const int nrow  = wn * 32 + (lane & 7) + ((lane >> 4) & 1) * 8;
    const int bkb   = ((lane >> 3) & 1) * 16;
    const uint32_t boff[2] = { sw_off(nrow, bkb), sw_off(nrow + 16, bkb) };

    const uint32_t aS[2] = { smem_u32(sA[0]), smem_u32(sA[1]) };
    const uint32_t bS[2] = { smem_u32(sB[0]), smem_u32(sB[1]) };

    float acc[2][4][4];
#pragma unroll
    for (int mf = 0; mf < 2; ++mf)
#pragma unroll
        for (int nf = 0; nf < 4; ++nf)
#pragma unroll
            for (int e = 0; e < 4; ++e) acc[mf][nf][e] = 0.f;

    // ---- prologue: tile 0
    {
        float4 ra[4], rb[2];
#pragma unroll
        for (int j = 0; j < 4; ++j) ra[j] = *(const float4*)(Ap + (size_t)j * 32 * K_);
#pragma unroll
        for (int j = 0; j < 2; ++j) rb[j] = *(const float4*)(Bp + (size_t)j * 32 * K_);
#pragma unroll
        for (int j = 0; j < 4; ++j) *(uint2*)(&sA[0][swA[j]]) = cvt4(ra[j]);
#pragma unroll
        for (int j = 0; j < 2; ++j) *(uint2*)(&sB[0][swB[j]]) = cvt4(rb[j]);
    }
    __syncthreads();

    int buf = 0;
    for (int kt = 0; kt < KT; ++kt) {
        const bool more = (kt + 1 < KT);
        float4 na[4], nb[2];
        if (more) {
            const int kc = (kt + 1) * BK;
#pragma unroll
            for (int j = 0; j < 4; ++j) na[j] = *(const float4*)(Ap + (size_t)j * 32 * K_ + kc);
#pragma unroll
            for (int j = 0; j < 2; ++j) nb[j] = *(const float4*)(Bp + (size_t)j * 32 * K_ + kc);
        }

        // ---- compute current tile: 2 k-slices of 16
#pragma unroll
        for (int ks = 0; ks < 2; ++ks) {
            const uint32_t kx = ks * 32;
            uint32_t af0[4], af1[4], bf0[4], bf1[4];
            ldsm4(af0, aS[buf] + (aoff[0] ^ kx));
            ldsm4(af1, aS[buf] + (aoff[1] ^ kx));
            ldsm4(bf0, bS[buf] + (boff[0] ^ kx));
            ldsm4(bf1, bS[buf] + (boff[1] ^ kx));

            mma16816(acc[0][0], af0, bf0 + 0);
            mma16816(acc[0][1], af0, bf0 + 2);
            mma16816(acc[0][2], af0, bf1 + 0);
            mma16816(acc[0][3], af0, bf1 + 2);
            mma16816(acc[1][0], af1, bf0 + 0);
            mma16816(acc[1][1], af1, bf0 + 2);
            mma16816(acc[1][2], af1, bf1 + 0);
            mma16816(acc[1][3], af1, bf1 + 2);
        }

        if (more) {
            const int nb_ = buf ^ 1;
#pragma unroll
            for (int j = 0; j < 4; ++j) *(uint2*)(&sA[nb_][swA[j]]) = cvt4(na[j]);
#pragma unroll
            for (int j = 0; j < 2; ++j) *(uint2*)(&sB[nb_][swB[j]]) = cvt4(nb[j]);
            __syncthreads();
            buf = nb_;
        }
    }

    // ---- epilogue ----
    const int tg = lane & 3;        // thread-in-group (n pairs)
    const int gr = lane >> 2;       // group id (rows)

#pragma unroll
    for (int mf = 0; mf < 2; ++mf) {
#pragma unroll
        for (int e = 0; e < 2; ++e) {
            const int row = bm + wm * 32 + mf * 16 + gr + e * 8;
            int bwin = 0, t = 0;
            if (MODE == 0) { bwin = row / NTOK; t = row - bwin * NTOK; }
#pragma unroll
            for (int nf = 0; nf < 4; ++nf) {
                const int n0 = bn + wn * 32 + nf * 8;
                const int nc = n0 + tg * 2;
                const float c0 = acc[mf][nf][e * 2 + 0];
                const float c1 = acc[mf][nf][e * 2 + 1];
                if (MODE == 0) {
                    const int which = n0 / DIM_;
                    const int hh    = (n0 - which * DIM_) >> 5;
                    const int cl    = (n0 & 31) + tg * 2;
                    const float scl = (which == 0) ? 0.17677669529663687f : 1.0f;
                    float* dst = (which == 0) ? g_Q : (which == 1) ? g_K : g_V;
                    float2 w;
                    w.x = (c0 + bias[nc + 0]) * scl;
                    w.y = (c1 + bias[nc + 1]) * scl;
                    *(float2*)(dst + ((size_t)(bwin * NH_ + hh) * NTOK + t) * HD_ + cl) = w;
                } else {
                    float2 w;
                    w.x = c0 + bias[nc + 0];
                    w.y = c1 + bias[nc + 1];
                    *(float2*)(out + (size_t)row * DIM_ + nc) = w;
                }
            }
        }
    }
}

// ---------------------------------------------------------------------------
// Window attention: one CTA (128 threads) per (window, head)
// scores: thread-per-row, q in regs, broadcast k loads (LDS-light)
// PV: float4 d-quads, one 128B wavefront per V row per warp
// ---------------------------------------------------------------------------
#define QSTR 36   // row stride (floats)

__global__ __launch_bounds__(128)
void attn_kernel(const float* __restrict__ table) {
    __shared__ float sq[NTOK * QSTR];
    __shared__ float sk[NTOK * QSTR];
    __shared__ float sv[NTOK * QSTR];
    __shared__ float sS[NTOK * NTOK];
    __shared__ float sbias[169];

    const int tid = threadIdx.x;
    const int bw  = blockIdx.x / NH_;
    const int h   = blockIdx.x % NH_;
    const size_t base = ((size_t)(bw * NH_ + h) * NTOK) * HD_;

    for (int i = tid; i < (NTOK * HD_) / 4; i += 128) {   // 392 float4
        int row = i >> 3;
        int c4  = (i & 7) * 4;
        int o   = row * QSTR + c4;
        *(float4*)(sq + o) = *(const float4*)(g_Q + base + i * 4);
        *(float4*)(sk + o) = *(const float4*)(g_K + base + i * 4);
        *(float4*)(sv + o) = *(const float4*)(g_V + base + i * 4);
    }
    for (int i = tid; i < 169; i += 128) sbias[i] = table[i * NH_ + h];
    __syncthreads();

    // ---- scores: S[n][m] = q[n].k[m] + bias(n,m) ----
    {
        const int n    = tid & 63;       // row (warp-uniform m below)
        const int half = tid >> 6;       // 0: m 0..24, 1: m 25..48
        const int m0   = half * 25;
        const bool act = (n < NTOK);
        float4 qv[8];
        if (act) {
            const float* qr = sq + n * QSTR;
#pragma unroll
            for (int j = 0; j < 8; ++j) qv[j] = *(const float4*)(qr + j * 4);
        }
        const int ndiv = n / 7;
        const int nmod = n - ndiv * 7;
#pragma unroll 5
        for (int mi = 0; mi < 25; ++mi) {
            const int m = m0 + mi;
            if (m < NTOK) {
                const float* kr = sk + m * QSTR;   // warp-uniform -> broadcast
                float acc = 0.f;
#pragma unroll
                for (int j = 0; j < 8; ++j) {
                    float4 kv = *(const float4*)(kr + j * 4);
                    acc += qv[j].x * kv.x + qv[j].y * kv.y
                         + qv[j].z * kv.z + qv[j].w * kv.w;
                }
                if (act) {
                    const int mdiv = m / 7;
                    const int mmod = m - mdiv * 7;
                    sS[n * NTOK + m] =
                        acc + sbias[(ndiv - mdiv + 6) * 13 + (nmod - mmod + 6)];
                }
            }
        }
    }
    __syncthreads();

    // ---- softmax over m (warp per row) ----
    {
        const int warp = tid >> 5, lane = tid & 31;
        for (int n = warp; n < NTOK; n += 4) {
            float v0 = sS[n * NTOK + lane];
            float v1 = (lane < 17) ? sS[n * NTOK + 32 + lane] : -1e30f;
            float mx = fmaxf(v0, v1);
#pragma unroll
            for (int o = 16; o > 0; o >>= 1)
                mx = fmaxf(mx, __shfl_xor_sync(0xffffffff, mx, o));
            float e0 = __expf(v0 - mx);
            float e1 = (lane < 17) ? __expf(v1 - mx) : 0.f;
            float sm = e0 + e1;
#pragma unroll
            for (int o = 16; o > 0; o >>= 1)
                sm += __shfl_xor_sync(0xffffffff, sm, o);
            float inv = __frcp_rn(sm);
            sS[n * NTOK + lane] = e0 * inv;
            if (lane < 17) sS[n * NTOK + 32 + lane] = e1 * inv;
        }
    }
    __syncthreads();

    // ---- O[n][d] = sum_m P[n][m] * V[m][d] ----
    {
        const int dq = (tid & 7) * 4;    // d quad
        for (int n = tid >> 3; n < NTOK; n += 16) {
            const float* pr = sS + n * NTOK;
            float4 acc = make_float4(0.f, 0.f, 0.f, 0.f);
#pragma unroll 7
            for (int m = 0; m < NTOK; ++m) {
                const float p = pr[m];
                float4 v = *(const float4*)(sv + m * QSTR + dq);
                acc.x += p * v.x; acc.y += p * v.y;
                acc.z += p * v.z; acc.w += p * v.w;
            }
            *(float4*)(g_AO + ((size_t)bw * NTOK + n) * DIM_ + h * HD_ + dq) = acc;
        }
    }
}

// ---------------------------------------------------------------------------
extern "C" void kernel_launch(void* const* d_in, const int* in_sizes, int n_in,
                              void* d_out, int out_size) {
    const float* x      = (const float*)d_in[0];
    const float* qkv_w  = (const float*)d_in[1];
    const float* qkv_b  = (const float*)d_in[2];
    const float* proj_w = (const float*)d_in[3];
    const float* proj_b = (const float*)d_in[4];
    const float* table  = (const float*)d_in[5];
    float* out = (float*)d_out;

    dim3 g1((3 * DIM_) / BN, M_ / BM);   // 18 x 784
    gemm_fp16<0><<<g1, 256>>>(x, qkv_w, qkv_b, nullptr);

    attn_kernel<<<BW_ * NH_, 128>>>(table);

    dim3 g3(DIM_ / BN, M_ / BM);         // 6 x 784
    gemm_fp16<1><<<g3, 256>>>(nullptr, proj_w, proj_b, out);
}

// round 6
// speedup vs baseline: 5.6723x; 2.3404x over previous
#include <cuda_runtime.h>
#include <cuda_fp16.h>
#include <cstdint>

// ---------------------------------------------------------------------------
// Problem constants
// ---------------------------------------------------------------------------
#define BW_   2048
#define NTOK  49
#define NH_   12
#define HD_   32
#define DIM_  384
#define M_    (BW_ * NTOK)   // 100352
#define K_    DIM_

// fp16 scratch (device globals; allocation in kernel_launch is forbidden)
__device__ __align__(16) __half g_xh[M_ * DIM_];
__device__ __align__(16) __half g_wh[4 * DIM_ * DIM_];   // qkv_w (3*384*384) then proj_w
__device__ __align__(16) __half g_Qh[BW_ * NH_ * NTOK * HD_];
__device__ __align__(16) __half g_Kh[BW_ * NH_ * NTOK * HD_];
__device__ __align__(16) __half g_Vh[BW_ * NH_ * NTOK * HD_];
__device__ __align__(16) __half g_AOh[M_ * DIM_];

// ---------------------------------------------------------------------------
// helpers
// ---------------------------------------------------------------------------
__device__ __forceinline__ uint32_t smem_u32(const void* p) {
    uint32_t a;
    asm("{ .reg .u64 t; cvta.to.shared.u64 t, %1; cvt.u32.u64 %0, t; }"
        : "=r"(a) : "l"(p));
    return a;
}

// 64B-row swizzle (rows of 32 fp16): conflict-free for ldmatrix + 16B stores
__device__ __forceinline__ uint32_t sw_off(int row, int kb) {
    return (uint32_t)(row * 64 + (kb ^ (((row >> 1) & 3) << 4)));
}

// 128B-row swizzle for the transposed-V tile (32 rows x 64 fp16)
__device__ __forceinline__ uint32_t vt_off(int row, int c) {
    return (uint32_t)(row * 128 + ((((c >> 4) ^ (row & 7)) << 4)) + (c & 15));
}

__device__ __forceinline__ void ldsm4(uint32_t* r, uint32_t a) {
    asm volatile("ldmatrix.sync.aligned.m8n8.x4.shared.b16 {%0,%1,%2,%3}, [%4];"
                 : "=r"(r[0]), "=r"(r[1]), "=r"(r[2]), "=r"(r[3]) : "r"(a));
}

__device__ __forceinline__ void mma16816(float* c, const uint32_t* a, const uint32_t* b) {
    asm volatile(
        "mma.sync.aligned.m16n8k16.row.col.f32.f16.f16.f32 "
        "{%0,%1,%2,%3}, {%4,%5,%6,%7}, {%8,%9}, {%0,%1,%2,%3};"
        : "+f"(c[0]), "+f"(c[1]), "+f"(c[2]), "+f"(c[3])
        : "r"(a[0]), "r"(a[1]), "r"(a[2]), "r"(a[3]), "r"(b[0]), "r"(b[1]));
}

__device__ __forceinline__ void cp16(uint32_t dst, const void* src) {
    asm volatile("cp.async.cg.shared.global [%0], [%1], 16;" :: "r"(dst), "l"(src));
}
#define CP_COMMIT() asm volatile("cp.async.commit_group;")
#define CP_WAIT(n)  asm volatile("cp.async.wait_group %0;" :: "n"(n))

__device__ __forceinline__ uint32_t h2u(__half2 h) { return *(uint32_t*)&h; }

// ---------------------------------------------------------------------------
// fp32 -> fp16 convert (pre-pass)
// ---------------------------------------------------------------------------
template <int DST>
__global__ void cvt_kernel(const float4* __restrict__ src, int n4) {
    __half* dst = (DST == 0) ? g_xh : (DST == 1) ? g_wh : g_wh + 3 * DIM_ * DIM_;
    int i = blockIdx.x * blockDim.x + threadIdx.x;
    if (i < n4) {
        float4 f = src[i];
        uint2 u;
        u.x = h2u(__floats2half2_rn(f.x, f.y));
        u.y = h2u(__floats2half2_rn(f.z, f.w));
        *(uint2*)(dst + (size_t)i * 4) = u;
    }
}

// ---------------------------------------------------------------------------
// fp16 GEMM (f32 acc): C[M,N] = A[M,K] * B[N,K]^T (+bias)
// MODE 0: A = g_xh, B = qkv weights, N=1152, epilogue -> fp16 Q/K/V scatter
// MODE 1: A = g_AOh, B = proj weights, N=384, epilogue -> fp32 out
// CTA 128x128x32, 8 warps (4m x 2n), warp tile 32x64, 3-stage cp.async.
// ---------------------------------------------------------------------------
#define BM 128
#define BN 128
#define BK 32
#define KT 12

template <int MODE>
__global__ __launch_bounds__(256, 2)
void gemm_h(const float* __restrict__ bias, float* __restrict__ out) {
    __shared__ __align__(16) __half sA[3][BM * BK];
    __shared__ __align__(16) __half sB[3][BN * BK];

    const __half* Ah = (MODE == 0) ? g_xh : g_AOh;
    const __half* Bh = (MODE == 0) ? g_wh : g_wh + 3 * DIM_ * DIM_;

    const int tid  = threadIdx.x;
    const int lane = tid & 31;
    const int wid  = tid >> 5;
    const int wm   = wid & 3;
    const int wn   = wid >> 2;
    const int bm   = blockIdx.y * BM;
    const int bn   = blockIdx.x * BN;

    // loader: thread -> rows (tid>>2, +64), 16B chunk (tid&3)
    const int lrow = tid >> 2;
    const int lc   = tid & 3;
    const __half* Asrc = Ah + (size_t)(bm + lrow) * K_ + lc * 8;
    const __half* Bsrc = Bh + (size_t)(bn + lrow) * K_ + lc * 8;
    const uint32_t sw0 = sw_off(lrow, lc * 16);
    const uint32_t sw1 = sw_off(lrow + 64, lc * 16);

    uint32_t aSb[3], bSb[3];
#pragma unroll
    for (int s = 0; s < 3; ++s) { aSb[s] = smem_u32(sA[s]); bSb[s] = smem_u32(sB[s]); }

    // fragment offsets
    const int arow = wm * 32 + (lane & 15);
    const uint32_t akb = ((lane >> 4) & 1) * 16;
    const uint32_t aoff0 = sw_off(arow, akb);
    const uint32_t aoff1 = sw_off(arow + 16, akb);
    const int nrB = (lane & 7) + ((lane >> 4) & 1) * 8;
    const uint32_t bkb = ((lane >> 3) & 1) * 16;
    uint32_t boff[4];
#pragma unroll
    for (int p = 0; p < 4; ++p) boff[p] = sw_off(wn * 64 + p * 16 + nrB, bkb);

    float acc[2][8][4];
#pragma unroll
    for (int mf = 0; mf < 2; ++mf)
#pragma unroll
        for (int f = 0; f < 8; ++f)
#pragma unroll
            for (int e = 0; e < 4; ++e) acc[mf][f][e] = 0.f;

    auto issue = [&](int kt, int st) {
        const __half* as = Asrc + kt * BK;
        const __half* bs = Bsrc + kt * BK;
        cp16(aSb[st] + sw0, as);
        cp16(aSb[st] + sw1, as + (size_t)64 * K_);
        cp16(bSb[st] + sw0, bs);
        cp16(bSb[st] + sw1, bs + (size_t)64 * K_);
        CP_COMMIT();
    };

    issue(0, 0);
    issue(1, 1);

    for (int kt = 0; kt < KT; ++kt) {
        if (kt < KT - 2) { CP_WAIT(1); } else { CP_WAIT(0); }
        __syncthreads();

        const int st = kt % 3;
        const uint32_t aB = aSb[st], bB = bSb[st];
#pragma unroll
        for (int ks = 0; ks < 2; ++ks) {
            const uint32_t kx = ks * 32;
            uint32_t af0[4], af1[4];
            ldsm4(af0, aB + (aoff0 ^ kx));
            ldsm4(af1, aB + (aoff1 ^ kx));
#pragma unroll
            for (int p = 0; p < 4; ++p) {
                uint32_t bf[4];
                ldsm4(bf, bB + (boff[p] ^ kx));
                mma16816(acc[0][2 * p],     af0, bf);
                mma16816(acc[0][2 * p + 1], af0, bf + 2);
                mma16816(acc[1][2 * p],     af1, bf);
                mma16816(acc[1][2 * p + 1], af1, bf + 2);
            }
        }
        if (kt + 2 < KT) issue(kt + 2, (kt + 2) % 3);
    }

    // ---- epilogue ----
    const int gr = lane >> 2, tg = lane & 3;

    if (MODE == 0) {
        const int which = bn / DIM_;          // uniform: 1152 = 3*384, BN=128 | 384
        const float scl = (which == 0) ? 0.17677669529663687f : 1.0f;
        __half* dst = (which == 0) ? g_Qh : (which == 1) ? g_Kh : g_Vh;
#pragma unroll
        for (int mf = 0; mf < 2; ++mf) {
#pragma unroll
            for (int e = 0; e < 2; ++e) {
                const int row = bm + wm * 32 + mf * 16 + gr + e * 8;
                const int bwin = row / NTOK;
                const int t = row - bwin * NTOK;
#pragma unroll
                for (int f = 0; f < 8; ++f) {
                    const int n = bn + wn * 64 + f * 8 + tg * 2;
                    const int hh = (n - which * DIM_) >> 5;
                    const int cl = n & 31;
                    float v0 = (acc[mf][f][e * 2 + 0] + bias[n + 0]) * scl;
                    float v1 = (acc[mf][f][e * 2 + 1] + bias[n + 1]) * scl;
                    *(__half2*)(dst + ((size_t)(bwin * NH_ + hh) * NTOK + t) * HD_ + cl) =
                        __floats2half2_rn(v0, v1);
                }
            }
        }
    } else {
#pragma unroll
        for (int mf = 0; mf < 2; ++mf) {
#pragma unroll
            for (int e = 0; e < 2; ++e) {
                const int row = bm + wm * 32 + mf * 16 + gr + e * 8;
#pragma unroll
                for (int f = 0; f < 8; ++f) {
                    const int n = bn + wn * 64 + f * 8 + tg * 2;
                    float2 w;
                    w.x = acc[mf][f][e * 2 + 0] + bias[n + 0];
                    w.y = acc[mf][f][e * 2 + 1] + bias[n + 1];
                    *(float2*)(out + (size_t)row * DIM_ + n) = w;
                }
            }
        }
    }
}

// ---------------------------------------------------------------------------
// Tensorized window attention: one CTA (128 thr / 4 warps) per (window, head)
// S = Q K^T (m64 pad, n64 pad, k32) -> bias+mask+softmax on fragments ->
// P (fp16, in regs, acc->A identity) x V^T (smem) -> AO fp16
// ---------------------------------------------------------------------------
__global__ __launch_bounds__(128)
void attn_tc(const float* __restrict__ table) {
    __shared__ __align__(16) __half sQ[64 * 32];
    __shared__ __align__(16) __half sK[64 * 32];
    __shared__ __align__(16) __half sVT[32 * 64];
    __shared__ float sbias[169];

    const int tid  = threadIdx.x;
    const int lane = tid & 31;
    const int w    = tid >> 5;
    const int bw   = blockIdx.x / NH_;
    const int h    = blockIdx.x % NH_;

    const __half* qg = g_Qh + (size_t)(bw * NH_ + h) * NTOK * HD_;
    const __half* kg = g_Kh + (size_t)(bw * NH_ + h) * NTOK * HD_;
    const __half* vg = g_Vh + (size_t)(bw * NH_ + h) * NTOK * HD_;
    const uint32_t sQb = smem_u32(sQ), sKb = smem_u32(sK), sVb = smem_u32(sVT);

    // zero V^T pad columns (tokens 48..63 -> bytes 96..127 of each of 32 rows)
    if (tid < 64) {
        const int r = tid >> 1, c = (6 + (tid & 1)) * 16;
        *(uint4*)((char*)sVT + vt_off(r, c)) = make_uint4(0, 0, 0, 0);
    }
    // load Q, K (49 rows x four 16B chunks)
    for (int i = tid; i < 196; i += 128) {
        const int r = i >> 2, c = (i & 3) * 16;
        uint4 q4 = *(const uint4*)(qg + r * HD_ + (i & 3) * 8);
        uint4 k4 = *(const uint4*)(kg + r * HD_ + (i & 3) * 8);
        *(uint4*)((char*)sQ + sw_off(r, c)) = q4;
        *(uint4*)((char*)sK + sw_off(r, c)) = k4;
    }
    for (int i = tid; i < 169; i += 128) sbias[i] = table[i * NH_ + h];
    __syncthreads();
    // V transpose scatter: VT[d][tok]
    for (int i = tid; i < 196; i += 128) {
        const int tok = i >> 2, d0 = (i & 3) * 8;
        uint4 v4 = *(const uint4*)(vg + tok * HD_ + d0);
        __half hv[8];
        *(uint4*)hv = v4;
#pragma unroll
        for (int j = 0; j < 8; ++j)
            *(__half*)((char*)sVT + vt_off(d0 + j, tok * 2)) = hv[j];
    }
    __syncthreads();

    const int gr = lane >> 2, tg = lane & 3;

    // ---- S = Q K^T : warp w -> rows w*16..+15, cols 0..63 (8 n8 frags)
    float sacc[8][4];
#pragma unroll
    for (int f = 0; f < 8; ++f)
#pragma unroll
        for (int e = 0; e < 4; ++e) sacc[f][e] = 0.f;

    const uint32_t aoff = sw_off(w * 16 + (lane & 15), ((lane >> 4) & 1) * 16);
    const int nrB = (lane & 7) + ((lane >> 4) & 1) * 8;
    const uint32_t bkb = ((lane >> 3) & 1) * 16;
#pragma unroll
    for (int ks = 0; ks < 2; ++ks) {
        const uint32_t kx = ks * 32;
        uint32_t af[4];
        ldsm4(af, sQb + (aoff ^ kx));
#pragma unroll
        for (int p = 0; p < 4; ++p) {
            uint32_t bf[4];
            ldsm4(bf, sKb + (sw_off(p * 16 + nrB, bkb) ^ kx));
            mma16816(sacc[2 * p],     af, bf);
            mma16816(sacc[2 * p + 1], af, bf + 2);
        }
    }

    // ---- bias + mask + softmax (rows r0 = w*16+gr, r1 = r0+8)
    const int r0 = w * 16 + gr, r1 = r0 + 8;
    const int r0d = r0 / 7, r0m = r0 - r0d * 7;
    const int r1d = r1 / 7, r1m = r1 - r1d * 7;
    float mx0 = -1e30f, mx1 = -1e30f;
#pragma unroll
    for (int f = 0; f < 8; ++f) {
#pragma unroll
        for (int c = 0; c < 2; ++c) {
            const int j = f * 8 + tg * 2 + c;
            const int jd = j / 7, jm = j - jd * 7;
            const bool jv = (j < NTOK);
            float s0 = -1e30f, s1 = -1e30f;
            if (jv) {
                float b0 = (r0 < NTOK) ? sbias[(r0d - jd + 6) * 13 + (r0m - jm + 6)] : 0.f;
                float b1 = (r1 < NTOK) ? sbias[(r1d - jd + 6) * 13 + (r1m - jm + 6)] : 0.f;
                s0 = sacc[f][c]     + b0;
                s1 = sacc[f][c + 2] + b1;
            }
            sacc[f][c]     = s0;
            sacc[f][c + 2] = s1;
            mx0 = fmaxf(mx0, s0);
            mx1 = fmaxf(mx1, s1);
        }
    }
    mx0 = fmaxf(mx0, __shfl_xor_sync(0xffffffffu, mx0, 1));
    mx0 = fmaxf(mx0, __shfl_xor_sync(0xffffffffu, mx0, 2));
    mx1 = fmaxf(mx1, __shfl_xor_sync(0xffffffffu, mx1, 1));
    mx1 = fmaxf(mx1, __shfl_xor_sync(0xffffffffu, mx1, 2));

    float sum0 = 0.f, sum1 = 0.f;
#pragma unroll
    for (int f = 0; f < 8; ++f) {
        float e0 = __expf(sacc[f][0] - mx0);
        float e1 = __expf(sacc[f][1] - mx0);
        float e2 = __expf(sacc[f][2] - mx1);
        float e3 = __expf(sacc[f][3] - mx1);
        sacc[f][0] = e0; sacc[f][1] = e1; sacc[f][2] = e2; sacc[f][3] = e3;
        sum0 += e0 + e1;
        sum1 += e2 + e3;
    }
    sum0 += __shfl_xor_sync(0xffffffffu, sum0, 1);
    sum0 += __shfl_xor_sync(0xffffffffu, sum0, 2);
    sum1 += __shfl_xor_sync(0xffffffffu, sum1, 1);
    sum1 += __shfl_xor_sync(0xffffffffu, sum1, 2);
    const float inv0 = __frcp_rn(sum0);
    const float inv1 = __frcp_rn(sum1);

    // ---- pack P into A-fragments (acc->A identity)
    uint32_t pa[4][4];
#pragma unroll
    for (int ks = 0; ks < 4; ++ks) {
        pa[ks][0] = h2u(__floats2half2_rn(sacc[2 * ks][0],     sacc[2 * ks][1]));
        pa[ks][1] = h2u(__floats2half2_rn(sacc[2 * ks][2],     sacc[2 * ks][3]));
        pa[ks][2] = h2u(__floats2half2_rn(sacc[2 * ks + 1][0], sacc[2 * ks + 1][1]));
        pa[ks][3] = h2u(__floats2half2_rn(sacc[2 * ks + 1][2], sacc[2 * ks + 1][3]));
    }

    // ---- O = P V : n = d (32 -> 2 ldsm pairs), k = tokens (4 kslices of 16)
    float oacc[4][4];
#pragma unroll
    for (int f = 0; f < 4; ++f)
#pragma unroll
        for (int e = 0; e < 4; ++e) oacc[f][e] = 0.f;

#pragma unroll
    for (int ks = 0; ks < 4; ++ks) {
        const int kbv = ks * 32 + ((lane >> 3) & 1) * 16;
#pragma unroll
        for (int p = 0; p < 2; ++p) {
            uint32_t bf[4];
            ldsm4(bf, sVb + vt_off(p * 16 + nrB, kbv));
            mma16816(oacc[2 * p],     pa[ks], bf);
            mma16816(oacc[2 * p + 1], pa[ks], bf + 2);
        }
    }

    // ---- store AO fp16 (normalize by row sums)
    if (r0 < NTOK) {
        __half* o = g_AOh + ((size_t)bw * NTOK + r0) * DIM_ + h * HD_;
#pragma unroll
        for (int f = 0; f < 4; ++f) {
            const int d = f * 8 + tg * 2;
            *(__half2*)(o + d) =
                __floats2half2_rn(oacc[f][0] * inv0, oacc[f][1] * inv0);
        }
    }
    if (r1 < NTOK) {
        __half* o = g_AOh + ((size_t)bw * NTOK + r1) * DIM_ + h * HD_;
#pragma unroll
        for (int f = 0; f < 4; ++f) {
            const int d = f * 8 + tg * 2;
            *(__half2*)(o + d) =
                __floats2half2_rn(oacc[f][2] * inv1, oacc[f][3] * inv1);
        }
    }
}

// ---------------------------------------------------------------------------
extern "C" void kernel_launch(void* const* d_in, const int* in_sizes, int n_in,
                              void* d_out, int out_size) {
    const float* x      = (const float*)d_in[0];
    const float* qkv_w  = (const float*)d_in[1];
    const float* qkv_b  = (const float*)d_in[2];
    const float* proj_w = (const float*)d_in[3];
    const float* proj_b = (const float*)d_in[4];
    const float* table  = (const float*)d_in[5];
    float* out = (float*)d_out;

    const int n4x = (M_ * DIM_) / 4;
    const int n4w = (3 * DIM_ * DIM_) / 4;
    const int n4p = (DIM_ * DIM_) / 4;
    cvt_kernel<0><<<(n4x + 255) / 256, 256>>>((const float4*)x, n4x);
    cvt_kernel<1><<<(n4w + 255) / 256, 256>>>((const float4*)qkv_w, n4w);
    cvt_kernel<2><<<(n4p + 255) / 256, 256>>>((const float4*)proj_w, n4p);

    gemm_h<0><<<dim3((3 * DIM_) / BN, M_ / BM), 256>>>(qkv_b, nullptr);

    attn_tc<<<BW_ * NH_, 128>>>(table);

    gemm_h<1><<<dim3(DIM_ / BN, M_ / BM), 256>>>(proj_b, out);
}